// round 2
// baseline (speedup 1.0000x reference)
#include <cuda_runtime.h>
#include <cuda_bf16.h>

#define T_STEPS  2048
#define BATCH    4096
#define INSZ     8
#define HID      20
#define G4       80
#define KV       28      // INSZ + HID
#define GROUPS   14      // thread groups per CTA
#define NGE      28      // batch elems per CTA (2 per thread group)
#define NTHREADS 280     // GROUPS * HID
#define ROWW     32      // padded smem row (floats): x[0:8], h[8:28], pad

__device__ __forceinline__ float sigmoid_f(float v) {
    return __fdividef(1.0f, 1.0f + __expf(-v));
}
__device__ __forceinline__ float tanh_f(float v) {
    return __fdividef(2.0f, 1.0f + __expf(-2.0f * v)) - 1.0f;
}

__global__ void __launch_bounds__(NTHREADS, 1)
lstm_kernel(const float* __restrict__ x,    // [T, B, 8]
            const float* __restrict__ Wih,  // [8, 80]
            const float* __restrict__ bih,  // [80]
            const float* __restrict__ Whh,  // [20, 80]
            const float* __restrict__ bhh,  // [80]
            const float* __restrict__ hx0,  // [1, 20]
            const float* __restrict__ cx0,  // [1, 20]
            float* __restrict__ out)        // [B, 20]
{
    __shared__ __align__(16) float sv[2][NGE][ROWW];

    const int tid = threadIdx.x;
    const int g   = tid / HID;            // 0..13
    const int j   = tid % HID;            // 0..19
    const int b0  = blockIdx.x * NGE + g;
    const int b1  = b0 + GROUPS;
    const bool ok0 = (b0 < BATCH);
    const bool ok1 = (b1 < BATCH);
    const int cb0 = ok0 ? b0 : 0;         // clamped for safe loads
    const int cb1 = ok1 ? b1 : 0;

    // ---- weights for unit j: 112 registers, shared by both batch elems ----
    float w[KV][4];
#pragma unroll
    for (int k = 0; k < INSZ; k++)
#pragma unroll
        for (int q = 0; q < 4; q++)
            w[k][q] = __ldg(&Wih[k * G4 + q * HID + j]);
#pragma unroll
    for (int k = 0; k < HID; k++)
#pragma unroll
        for (int q = 0; q < 4; q++)
            w[INSZ + k][q] = __ldg(&Whh[k * G4 + q * HID + j]);

    float bias[4];
#pragma unroll
    for (int q = 0; q < 4; q++)
        bias[q] = __ldg(&bih[q * HID + j]) + __ldg(&bhh[q * HID + j]);

    float h0 = hx0[j], c0 = cx0[j];
    float h1 = h0,     c1 = c0;

    const float4* x4 = reinterpret_cast<const float4*>(x);
    // x float4 index for (t, b, half): (t*BATCH + b)*2 + half

    // ---- prologue: sv[0] <- [x_0 ; h_init]; prefetch x_1 into regs ----
    float4 xn0 = make_float4(0.f, 0.f, 0.f, 0.f);
    float4 xn1 = xn0;
    if (j < 2) {
        float4 a0 = x4[(0 * BATCH + cb0) * 2 + j];
        float4 a1 = x4[(0 * BATCH + cb1) * 2 + j];
        *reinterpret_cast<float4*>(&sv[0][g][j * 4]) = a0;
        *reinterpret_cast<float4*>(&sv[0][g + GROUPS][j * 4]) = a1;
        xn0 = x4[(1 * BATCH + cb0) * 2 + j];
        xn1 = x4[(1 * BATCH + cb1) * 2 + j];
    }
    sv[0][g][INSZ + j]          = h0;
    sv[0][g + GROUPS][INSZ + j] = h1;
    __syncthreads();

    int cur = 0;
    for (int t = 0; t < T_STEPS; t++) {
        const int nxt = cur ^ 1;

        // prefetch x_{t+2} (consumed at end of step t+1) — hides DRAM latency
        float4 xp0 = make_float4(0.f, 0.f, 0.f, 0.f);
        float4 xp1 = xp0;
        if (j < 2 && (t + 2) < T_STEPS) {
            xp0 = x4[((t + 2) * BATCH + cb0) * 2 + j];
            xp1 = x4[((t + 2) * BATCH + cb1) * 2 + j];
        }

        float a00 = bias[0], a01 = bias[1], a02 = bias[2], a03 = bias[3];
        float a10 = bias[0], a11 = bias[1], a12 = bias[2], a13 = bias[3];

        const float4* r0 = reinterpret_cast<const float4*>(sv[cur][g]);
        const float4* r1 = reinterpret_cast<const float4*>(sv[cur][g + GROUPS]);
#pragma unroll
        for (int kc = 0; kc < KV / 4; kc++) {
            const float4 u = r0[kc];
            const float4 v = r1[kc];
            const int k = kc * 4;
            const float ua[4] = {u.x, u.y, u.z, u.w};
            const float va[4] = {v.x, v.y, v.z, v.w};
#pragma unroll
            for (int s = 0; s < 4; s++) {
                a00 = fmaf(ua[s], w[k + s][0], a00);
                a01 = fmaf(ua[s], w[k + s][1], a01);
                a02 = fmaf(ua[s], w[k + s][2], a02);
                a03 = fmaf(ua[s], w[k + s][3], a03);
                a10 = fmaf(va[s], w[k + s][0], a10);
                a11 = fmaf(va[s], w[k + s][1], a11);
                a12 = fmaf(va[s], w[k + s][2], a12);
                a13 = fmaf(va[s], w[k + s][3], a13);
            }
        }

        // activations + state update (elem 0)
        {
            float ii = sigmoid_f(a00);
            float ff = sigmoid_f(a01);
            float gg = tanh_f(a02);
            float oo = sigmoid_f(a03);
            c0 = ff * c0 + ii * gg;
            h0 = oo * tanh_f(c0);
        }
        // (elem 1)
        {
            float ii = sigmoid_f(a10);
            float ff = sigmoid_f(a11);
            float gg = tanh_f(a12);
            float oo = sigmoid_f(a13);
            c1 = ff * c1 + ii * gg;
            h1 = oo * tanh_f(c1);
        }

        if (t + 1 < T_STEPS) {
            sv[nxt][g][INSZ + j]          = h0;
            sv[nxt][g + GROUPS][INSZ + j] = h1;
            if (j < 2) {
                *reinterpret_cast<float4*>(&sv[nxt][g][j * 4]) = xn0;
                *reinterpret_cast<float4*>(&sv[nxt][g + GROUPS][j * 4]) = xn1;
                xn0 = xp0;
                xn1 = xp1;
            }
            __syncthreads();
        }
        cur = nxt;
    }

    if (ok0) out[b0 * HID + j] = h0;
    if (ok1) out[b1 * HID + j] = h1;
}

extern "C" void kernel_launch(void* const* d_in, const int* in_sizes, int n_in,
                              void* d_out, int out_size) {
    const float* x   = (const float*)d_in[0];
    const float* Wih = (const float*)d_in[1];
    const float* bih = (const float*)d_in[2];
    const float* Whh = (const float*)d_in[3];
    const float* bhh = (const float*)d_in[4];
    const float* hx0 = (const float*)d_in[5];
    const float* cx0 = (const float*)d_in[6];
    float* out = (float*)d_out;

    const int grid = (BATCH + NGE - 1) / NGE;  // 147
    lstm_kernel<<<grid, NTHREADS>>>(x, Wih, bih, Whh, bhh, hx0, cx0, out);
}